// round 14
// baseline (speedup 1.0000x reference)
#include <cuda_runtime.h>
#include <cstdint>

// MultiLIF: I[B=32, L=2048, K=512] -> (spikes[B,L,K], spike_series[B,L,K])
// d_out: spikes (B*L*K floats) then spike_series.
//
// R14: fused producer/consumer pipeline. R13 ran phase1 (recurrence+bitmask,
// ~67us, latency-bound) and phase2 (store flood, 44.6us, BW-bound) serially.
// Now one kernel: blocks 0..127 = R13 phase1, publishing a progress flag per
// 64-step chunk (threadfence + atomicAdd release); blocks 128..1151 = R13
// phase2 writers, each spinning (volatile + nanosleep, then threadfence
// acquire) until its chunk's flag shows all 128 compute blocks done. Writers
// drain faster than compute produces -> total ~ phase1 + 1-chunk tail.
// Deadlock-free: compute blocks are bids 0..127, always resident in wave 1.

static constexpr int B_ = 32;
static constexpr int L_ = 2048;
static constexpr int K_ = 512;
static constexpr int NEURONS = B_ * K_;          // 16384
static constexpr int UNROLL = 8;
static constexpr int NBUF = 8;
static constexpr int NBATCH = L_ / UNROLL;       // 256
static constexpr int GROUPS = NBATCH / NBUF;     // 32 chunks of 64 steps
static constexpr int STRIDE = UNROLL * K_;
static constexpr int CHUNK = 64;
static constexpr int NCHUNK = L_ / CHUNK;        // 32
static constexpr int NW32 = L_ / 32;             // 64 bit-windows
static constexpr int NCOMPUTE = 128;             // compute blocks
static constexpr int WPC = 32;                   // writer blocks per chunk
static constexpr int NWRITER = NCHUNK * WPC;     // 1024
static constexpr int NBLOCKS = NCOMPUTE + NWRITER; // 1152

__device__ uint32_t g_bits[NW32][NEURONS];       // 4 MB  [t/32][neuron]
__device__ float    g_nckpt[NCHUNK][NEURONS];    // 2 MB  [chunk][neuron]
__device__ int      g_prog[NCHUNK];              // flags

__device__ __forceinline__ float div_const_rn(float x, float b, float y)
{
    // Markstein: correctly-rounded RN(x/b), y = RN(1/b). Branch-free;
    // == __fdiv_rn for all values reachable here.
    float q0 = __fmul_rn(x, y);
    float r  = __fmaf_rn(-b, q0, x);
    return __fmaf_rn(r, y, q0);
}

__global__ void reset_prog()
{
    if (threadIdx.x < NCHUNK) g_prog[threadIdx.x] = 0;
}

__global__ __launch_bounds__(128, 1)
void lif_fused(const float* __restrict__ I,
               float* __restrict__ spikes,
               float* __restrict__ series)
{
    int bid = blockIdx.x;

    if (bid < NCOMPUTE) {
        // ------------------------ compute role (== R13 phase1) -------------
        int gid = bid * 128 + threadIdx.x;           // neuron 0..16383
        int b = gid >> 9;
        int k = gid & (K_ - 1);

        const float* ip = I + (int64_t)b * L_ * K_ + k;
        const float c2 = -0.5f - div_const_rn(-0.5f, 20.0f, 0.05f);

        float buf[NBUF][UNROLL];
#pragma unroll
        for (int p = 0; p < NBUF - 1; p++)
#pragma unroll
            for (int u = 0; u < UNROLL; u++)
                buf[p][u] = __ldcs(ip + (int64_t)(p * UNROLL + u) * K_);

        const float* ipn = ip + (int64_t)(NBUF - 1) * STRIDE;
        float uv = 0.0f, a = 0.0f, n = 0.0f;
        bool fire = false;
        uint32_t bits = 0;

#pragma unroll 1
        for (int g = 0; g < GROUPS; g++) {
            __stcs(&g_nckpt[g][gid], n);             // n BEFORE this chunk
#pragma unroll
            for (int p = 0; p < NBUF; p++) {         // p compile-time
                int loadidx = g * NBUF + p + (NBUF - 1);
                const float* lp = (loadidx < NBATCH) ? ipn : ip;
#pragma unroll
                for (int u = 0; u < UNROLL; u++)
                    buf[(p + NBUF - 1) & (NBUF - 1)][u] = __ldcs(lp + u * K_);
                ipn += STRIDE;

#pragma unroll
                for (int u = 0; u < UNROLL; u++) {
                    float It = buf[p][u];
                    float th = 1.0f + 1.5f * a;
                    float uA = (uv - div_const_rn(uv, 20.0f, 0.05f)) + It;
                    float uB = c2 + It;
                    float un = fire ? uB : uA;
                    bool f = (un >= th);
                    float s = f ? 1.0f : 0.0f;
                    bits |= (f ? 1u : 0u) << (((p & 3) * UNROLL) + u);
                    a = (a - div_const_rn(a, 100.0f, 0.01f)) + s;
                    uv = un; fire = f;
                }
                if ((p & 3) == 3) {
                    __stcs(&g_bits[g * 2 + (p >> 2)][gid], bits);
                    n = n + (float)__popc(bits);     // exact integer adds
                    bits = 0;
                }
            }
            // publish chunk g: release
            __threadfence();
            __syncthreads();
            if (threadIdx.x == 0) atomicAdd(&g_prog[g], 1);
        }
    } else {
        // ------------------------ writer role (== R13 phase2) --------------
        int w = bid - NCOMPUTE;                      // 0..1023
        int c = w >> 5;                              // chunk 0..31
        int local = (w & 31) * 128 + threadIdx.x;    // 0..4095
        int nbase = local * 4;
        int b = nbase >> 9;
        int k = nbase & (K_ - 1);
        int t0 = c * CHUNK;

        // acquire chunk c
        if (threadIdx.x == 0) {
            volatile const int* pf = &g_prog[c];
            while (*pf < NCOMPUTE) __nanosleep(128);
        }
        __syncthreads();
        __threadfence();

        const float4* ck = (const float4*)&g_nckpt[c][nbase];
        float4 n4 = __ldcs(ck);

        int64_t base = ((int64_t)b * L_ + t0) * K_ + k;
        float4* sp = (float4*)(spikes + base);
        float4* np = (float4*)(series + base);
        const int s4 = K_ / 4;

        uint4 w0 = __ldcs((const uint4*)&g_bits[t0 >> 5][nbase]);
        uint4 w1 = __ldcs((const uint4*)&g_bits[(t0 >> 5) + 1][nbase]);

#pragma unroll 1
        for (int wi = 0; wi < CHUNK / 32; wi++) {    // 2 windows of 32 steps
            uint4 cur = (wi == 0) ? w0 : w1;
#pragma unroll
            for (int u = 0; u < 32; u++) {
                float4 s;
                s.x = ((cur.x >> u) & 1u) ? 1.0f : 0.0f;
                s.y = ((cur.y >> u) & 1u) ? 1.0f : 0.0f;
                s.z = ((cur.z >> u) & 1u) ? 1.0f : 0.0f;
                s.w = ((cur.w >> u) & 1u) ? 1.0f : 0.0f;
                n4.x += s.x; n4.y += s.y; n4.z += s.z; n4.w += s.w;
                __stcs(sp + u * s4, s);
                __stcs(np + u * s4, n4);
            }
            sp += 32 * s4; np += 32 * s4;
        }
    }
}

extern "C" void kernel_launch(void* const* d_in, const int* in_sizes, int n_in,
                              void* d_out, int out_size)
{
    const float* I = (const float*)d_in[0];
    float* spikes = (float*)d_out;
    float* series = (float*)d_out + (int64_t)B_ * L_ * K_;

    reset_prog<<<1, 32>>>();
    lif_fused<<<NBLOCKS, 128>>>(I, spikes, series);
}

// round 15
// speedup vs baseline: 1.3087x; 1.3087x over previous
#include <cuda_runtime.h>
#include <cstdint>

// MultiLIF: I[B=32, L=2048, K=512] -> (spikes[B,L,K], spike_series[B,L,K])
// d_out: spikes (B*L*K floats) then spike_series.
//
// R15: intra-block producer/consumer fusion. 128 blocks x 256 threads.
// Warps 0-3: R13 phase1 recurrence (compile-time ring, bit-packed spikes,
//   popc-exact n); per 64-step chunk publish 2 mask words + n checkpoint
//   per neuron into double-buffered smem.
// Warps 4-7: writers for the PREVIOUS chunk: each thread = 4 adjacent
//   neurons x 16 steps; s from bits (exact {0,1}), n from checkpoint +
//   popc prefix (exact integers -> bit-identical); float4 stores.
// One textual __syncthreads per chunk iteration (33 arrivals/thread).
// No global scratch, no inter-block sync, single launch.

static constexpr int B_ = 32;
static constexpr int L_ = 2048;
static constexpr int K_ = 512;
static constexpr int NEURONS = B_ * K_;          // 16384
static constexpr int UNROLL = 8;
static constexpr int NBUF = 8;
static constexpr int NBATCH = L_ / UNROLL;       // 256
static constexpr int GROUPS = NBATCH / NBUF;     // 32 chunks of 64 steps
static constexpr int STRIDE = UNROLL * K_;
static constexpr int CHUNK = 64;

__device__ __forceinline__ float div_const_rn(float x, float b, float y)
{
    // Markstein: correctly-rounded RN(x/b), y = RN(1/b). Branch-free;
    // == __fdiv_rn for all values reachable here.
    float q0 = __fmul_rn(x, y);
    float r  = __fmaf_rn(-b, q0, x);
    return __fmaf_rn(r, y, q0);
}

__global__ __launch_bounds__(256, 1)
void lif_fused(const float* __restrict__ I,
               float* __restrict__ spikes,
               float* __restrict__ series)
{
    __shared__ uint32_t sbits[2][2][128];   // [slot][window][neuron-in-block]
    __shared__ float    sn[2][128];         // [slot][neuron] n at chunk start

    const int tid = threadIdx.x;
    const int bid = blockIdx.x;
    const bool is_compute = (tid < 128);

    // ---------------- compute-role persistent state ----------------
    int gid = bid * 128 + (tid & 127);      // this block's neuron range
    int b = gid >> 9;
    int k = gid & (K_ - 1);
    const float* ip = I + (int64_t)b * L_ * K_ + k;
    const float c2 = -0.5f - div_const_rn(-0.5f, 20.0f, 0.05f);

    float buf[NBUF][UNROLL];
    const float* ipn = ip + (int64_t)(NBUF - 1) * STRIDE;
    float uv = 0.0f, a = 0.0f, n = 0.0f;
    bool fire = false;

    if (is_compute) {
#pragma unroll
        for (int p = 0; p < NBUF - 1; p++)
#pragma unroll
            for (int u = 0; u < UNROLL; u++)
                buf[p][u] = __ldcs(ip + (int64_t)(p * UNROLL + u) * K_);
    }

    // ---------------- writer-role constants ----------------
    const int w    = tid & 127;             // writer index 0..127
    const int tgrp = w >> 5;                // 16-step subrange 0..3
    const int nb   = (w & 31) * 4;          // first of 4 owned local neurons
    const int wk   = ((bid * 128 + nb) & (K_ - 1));
    const int wb   = (bid * 128 + nb) >> 9;
    const int s4   = K_ / 4;                // float4 stride per timestep
    const uint32_t m0 = (tgrp == 0) ? 0u : (tgrp == 1) ? 0xFFFFu : 0xFFFFFFFFu;
    const uint32_t m1 = (tgrp == 3) ? 0xFFFFu : 0u;
    const int sh = (tgrp & 1) * 16;

#pragma unroll 1
    for (int i = 0; i <= GROUPS; i++) {
        if (is_compute) {
            if (i < GROUPS) {
                int slot = i & 1;
                sn[slot][tid] = n;               // n BEFORE this chunk
                uint32_t bits = 0;
#pragma unroll
                for (int p = 0; p < NBUF; p++) { // p compile-time
                    int loadidx = i * NBUF + p + (NBUF - 1);
                    const float* lp = (loadidx < NBATCH) ? ipn : ip;
#pragma unroll
                    for (int u = 0; u < UNROLL; u++)
                        buf[(p + NBUF - 1) & (NBUF - 1)][u] = __ldcs(lp + u * K_);
                    ipn += STRIDE;

#pragma unroll
                    for (int u = 0; u < UNROLL; u++) {
                        float It = buf[p][u];
                        float th = 1.0f + 1.5f * a;
                        float uA = (uv - div_const_rn(uv, 20.0f, 0.05f)) + It;
                        float uB = c2 + It;
                        float un = fire ? uB : uA;
                        bool f = (un >= th);
                        float s = f ? 1.0f : 0.0f;
                        bits |= (f ? 1u : 0u) << (((p & 3) * UNROLL) + u);
                        a = (a - div_const_rn(a, 100.0f, 0.01f)) + s;
                        uv = un; fire = f;
                    }
                    if ((p & 3) == 3) {          // 32-step window complete
                        sbits[slot][p >> 2][tid] = bits;
                        n = n + (float)__popc(bits);   // exact integer adds
                        bits = 0;
                    }
                }
            }
        } else {
            if (i > 0) {
                int c = i - 1;
                int slot = c & 1;
                uint4 W0 = *(const uint4*)&sbits[slot][0][nb];
                uint4 W1 = *(const uint4*)&sbits[slot][1][nb];
                float4 ck = *(const float4*)&sn[slot][nb];

                float4 n4;
                n4.x = ck.x + (float)(__popc(W0.x & m0) + __popc(W1.x & m1));
                n4.y = ck.y + (float)(__popc(W0.y & m0) + __popc(W1.y & m1));
                n4.z = ck.z + (float)(__popc(W0.z & m0) + __popc(W1.z & m1));
                n4.w = ck.w + (float)(__popc(W0.w & m0) + __popc(W1.w & m1));

                uint4 cw;
                cw.x = (tgrp >= 2) ? W1.x : W0.x;
                cw.y = (tgrp >= 2) ? W1.y : W0.y;
                cw.z = (tgrp >= 2) ? W1.z : W0.z;
                cw.w = (tgrp >= 2) ? W1.w : W0.w;

                int t0 = c * CHUNK + tgrp * 16;
                int64_t base = ((int64_t)wb * L_ + t0) * K_ + wk;
                float4* sp = (float4*)(spikes + base);
                float4* np = (float4*)(series + base);

#pragma unroll
                for (int u = 0; u < 16; u++) {
                    float4 s;
                    s.x = ((cw.x >> (sh + u)) & 1u) ? 1.0f : 0.0f;
                    s.y = ((cw.y >> (sh + u)) & 1u) ? 1.0f : 0.0f;
                    s.z = ((cw.z >> (sh + u)) & 1u) ? 1.0f : 0.0f;
                    s.w = ((cw.w >> (sh + u)) & 1u) ? 1.0f : 0.0f;
                    n4.x += s.x; n4.y += s.y; n4.z += s.z; n4.w += s.w;
                    __stcs(sp + u * s4, s);
                    __stcs(np + u * s4, n4);
                }
            }
        }
        __syncthreads();   // single textual barrier, GROUPS+1 arrivals/thread
    }
}

extern "C" void kernel_launch(void* const* d_in, const int* in_sizes, int n_in,
                              void* d_out, int out_size)
{
    const float* I = (const float*)d_in[0];
    float* spikes = (float*)d_out;
    float* series = (float*)d_out + (int64_t)B_ * L_ * K_;

    lif_fused<<<128, 256>>>(I, spikes, series);
}

// round 16
// speedup vs baseline: 1.3601x; 1.0392x over previous
#include <cuda_runtime.h>
#include <cstdint>

// MultiLIF: I[B=32, L=2048, K=512] -> (spikes[B,L,K], spike_series[B,L,K])
// d_out: spikes (B*L*K floats) then spike_series.
//
// R16: three-duty fusion, compute warps do ZERO global memory.
//  Warps 0-3 (compute): pure LIF recurrence; input via conflict-free LDS from
//    a double-buffered smem tile; spikes bit-packed (1 u32 / 32 steps); n via
//    exact popc. No LDG, no ring, no pointers -> minimal regs, short loop.
//  Warps 4-7 (writers): per iteration i, (a) issue coalesced float4 LDGs of
//    input chunk i, (b) stream chunk i-2's outputs (s from bits, n from
//    checkpoint + popc prefix; all exact), (c) STS the loaded input.
//  One textual __syncthreads; 66 iterations; slot parity makes all smem
//  reuse barrier-separated. 128 blocks x 256 threads.

static constexpr int B_ = 32;
static constexpr int L_ = 2048;
static constexpr int K_ = 512;
static constexpr int NPB = 128;              // neurons per block
static constexpr int CHUNK = 32;             // steps per chunk
static constexpr int NCH = L_ / CHUNK;       // 64 chunks
static constexpr int ITER = NCH + 2;         // 66 pipeline iterations

__device__ __forceinline__ float div_const_rn(float x, float b, float y)
{
    // Markstein: correctly-rounded RN(x/b), y = RN(1/b). Branch-free;
    // == __fdiv_rn for all values reachable here.
    float q0 = __fmul_rn(x, y);
    float r  = __fmaf_rn(-b, q0, x);
    return __fmaf_rn(r, y, q0);
}

__global__ __launch_bounds__(256, 1)
void lif_fused(const float* __restrict__ I,
               float* __restrict__ spikes,
               float* __restrict__ series)
{
    __shared__ float    sin_[2][CHUNK][NPB]; // 32 KB input tiles
    __shared__ uint32_t sbits[2][NPB];       // spike bits per chunk
    __shared__ float    sn[2][NPB];          // n at chunk start

    const int tid = threadIdx.x;
    const int bid = blockIdx.x;
    const bool is_compute = (tid < NPB);

    // block's neuron range: bid*128 .. +127 (same b, contiguous k)
    const int b_blk = (bid * NPB) >> 9;             // batch index
    const int kbase = (bid * NPB) & (K_ - 1);       // k offset
    const int64_t in_base = (int64_t)b_blk * L_ * K_ + kbase;

    // ---------------- compute state ----------------
    const float c2 = -0.5f - div_const_rn(-0.5f, 20.0f, 0.05f);
    float uv = 0.0f, a = 0.0f, n = 0.0f;
    bool fire = false;

    // ---------------- writer constants ----------------
    const int w    = tid & (NPB - 1);        // writer index 0..127
    const int tgrp = w >> 5;                 // 8-step subrange 0..3
    const int nb   = (w & 31) * 4;           // first of 4 owned local neurons
    const int gn   = bid * NPB + nb;
    const int wb   = gn >> 9;
    const int wk   = gn & (K_ - 1);
    const int s4   = K_ / 4;                 // float4 stride per timestep
    const uint32_t premask = (tgrp == 0) ? 0u : ((1u << (tgrp * 8)) - 1u);
    const int sh = tgrp * 8;

#pragma unroll 1
    for (int i = 0; i < ITER; i++) {
        if (is_compute) {
            if (i >= 1 && i <= NCH) {
                int c = i - 1;
                int slot = c & 1;
                sn[slot][tid] = n;                    // n BEFORE this chunk
                uint32_t bits = 0;
#pragma unroll
                for (int u = 0; u < CHUNK; u++) {
                    float It = sin_[slot][u][tid];
                    float th = 1.0f + 1.5f * a;
                    float uA = (uv - div_const_rn(uv, 20.0f, 0.05f)) + It;
                    float uB = c2 + It;
                    float un = fire ? uB : uA;
                    bool f = (un >= th);
                    float s = f ? 1.0f : 0.0f;
                    bits |= (f ? 1u : 0u) << u;       // compile-time position
                    a = (a - div_const_rn(a, 100.0f, 0.01f)) + s;
                    uv = un; fire = f;
                }
                sbits[slot][tid] = bits;
                n = n + (float)__popc(bits);          // exact integer adds
            }
        } else {
            // (a) issue input loads for chunk i (latency overlapped by (b))
            float4 vdat[8];
            if (i < NCH) {
                int t0 = i * CHUNK;
#pragma unroll
                for (int j = 0; j < 8; j++) {
                    int flat4 = j * NPB + w;          // float4 index in tile
                    int step  = flat4 >> 5;           // 32 float4 per step
                    int col4  = flat4 & 31;
                    vdat[j] = __ldcs((const float4*)
                        (I + in_base + (int64_t)(t0 + step) * K_) + col4);
                }
            }
            // (b) store outputs for chunk i-2
            if (i >= 2) {
                int c = i - 2;
                int slot = c & 1;
                uint4 W = *(const uint4*)&sbits[slot][nb];
                float4 ck = *(const float4*)&sn[slot][nb];

                float4 n4;
                n4.x = ck.x + (float)__popc(W.x & premask);
                n4.y = ck.y + (float)__popc(W.y & premask);
                n4.z = ck.z + (float)__popc(W.z & premask);
                n4.w = ck.w + (float)__popc(W.w & premask);

                int t0c = c * CHUNK + tgrp * 8;
                int64_t base = ((int64_t)wb * L_ + t0c) * K_ + wk;
                float4* sp = (float4*)(spikes + base);
                float4* np = (float4*)(series + base);
#pragma unroll
                for (int u = 0; u < 8; u++) {
                    float4 s;
                    s.x = ((W.x >> (sh + u)) & 1u) ? 1.0f : 0.0f;
                    s.y = ((W.y >> (sh + u)) & 1u) ? 1.0f : 0.0f;
                    s.z = ((W.z >> (sh + u)) & 1u) ? 1.0f : 0.0f;
                    s.w = ((W.w >> (sh + u)) & 1u) ? 1.0f : 0.0f;
                    n4.x += s.x; n4.y += s.y; n4.z += s.z; n4.w += s.w;
                    __stcs(sp + u * s4, s);
                    __stcs(np + u * s4, n4);
                }
            }
            // (c) deposit loaded input into smem tile
            if (i < NCH) {
                int islot = i & 1;
#pragma unroll
                for (int j = 0; j < 8; j++) {
                    int flat4 = j * NPB + w;
                    int step  = flat4 >> 5;
                    int col4  = flat4 & 31;
                    *(float4*)&sin_[islot][step][col4 * 4] = vdat[j];
                }
            }
        }
        __syncthreads();   // single textual barrier, ITER arrivals/thread
    }
}

extern "C" void kernel_launch(void* const* d_in, const int* in_sizes, int n_in,
                              void* d_out, int out_size)
{
    const float* I = (const float*)d_in[0];
    float* spikes = (float*)d_out;
    float* series = (float*)d_out + (int64_t)B_ * L_ * K_;

    lif_fused<<<128, 256>>>(I, spikes, series);
}